// round 14
// baseline (speedup 1.0000x reference)
#include <cuda_runtime.h>
#include <cstdint>

// RandomShiftsAug == integer shifted gather with edge clamp:
//   out[n,c,j,i] = x[n,c, clamp(j+sy-4,0,83), clamp(i+sx-4,0,83)]
//
// R14 = R13 (both streams engine-driven: cp.async.bulk in AND out -- the only
// change in 13 rounds that raised the DRAM rate, 5.49->5.66 TB/s) with the
// serial middle collapsed:
//  - vertical shift folded into the bulk-load: sy*336B is 16B-aligned, so we
//    load the 84-|sy| valid source rows straight into their destination row
//    slots; vertical clamp becomes a clamped smem ROW INDEX at read time.
//  - the remaining in-place hazard is horizontal-only -> 2 phases (rows <42,
//    rows >=42; boundary-clamped reads stay inside their own phase's range),
//    3 barriers instead of 8, half the smem shuffle traffic.
//  - split bulk-store: rows 0..41 issued right after phase A, overlapping the
//    write stream with phase B compute; one wait_group 0 at the end.

#define N_   512
#define C_   9
#define H_   84
#define W_   84
#define PAD_ 4

#define SLICE       (H_ * W_)          // 7056 floats
#define ROW_BYTES   (W_ * 4)           // 336 B (16B-aligned)
#define SLICE_BYTES (SLICE * 4)        // 28224 B
#define THREADS     252                // 84 cols x 3 row phases
#define HALF_ROWS   42
#define HALF_BYTES  (HALF_ROWS * ROW_BYTES)

__device__ __forceinline__ uint32_t smem_u32(const void* p) {
    return (uint32_t)__cvta_generic_to_shared(p);
}

__global__ __launch_bounds__(THREADS, 8) void random_shift_r14_kernel(
    const float* __restrict__ x,
    const int*   __restrict__ shift,
    float*       __restrict__ out)
{
    __shared__ alignas(128) float s[SLICE];
    __shared__ alignas(8)  uint64_t mbar;

    const int nc  = blockIdx.x;            // (n*C + c)
    const int n   = nc / C_;
    const int tid = threadIdx.x;

    const uint32_t bar = smem_u32(&mbar);

    const int sx = __ldg(&shift[2 * n + 0]) - PAD_;   // [-4,4], block-uniform
    const int sy = __ldg(&shift[2 * n + 1]) - PAD_;

    if (tid == 0) {
        asm volatile("mbarrier.init.shared.b64 [%0], 1;" :: "r"(bar));
    }
    __syncthreads();

    // ---- bulk-load with the vertical shift folded in ----
    // valid source rows: max(sy,0) .. 83+min(sy,0)  -> 84-|sy| rows
    // they land at smem rows max(-sy,0) .. (identity mapping j <- j+sy)
    const int asy      = (sy >= 0) ? sy : -sy;
    const int src_row0 = (sy >= 0) ? sy : 0;
    const int dst_row0 = (sy >= 0) ? 0  : -sy;
    const uint32_t ld_bytes = (uint32_t)((H_ - asy) * ROW_BYTES);

    if (tid == 0) {
        asm volatile("mbarrier.arrive.expect_tx.shared.b64 _, [%0], %1;"
                     :: "r"(bar), "r"(ld_bytes) : "memory");
        asm volatile(
            "cp.async.bulk.shared::cluster.global.mbarrier::complete_tx::bytes "
            "[%0], [%1], %2, [%3];"
            :: "r"(smem_u32(s + dst_row0 * W_)),
               "l"(x + (long)nc * SLICE + src_row0 * W_),
               "r"(ld_bytes), "r"(bar)
            : "memory");
    }

    const int i  = tid % W_;               // column, 0..83
    const int j0 = tid / W_;               // row phase, 0..2
    const int srcx = min(max(i + sx, 0), W_ - 1);

    // valid smem row range after the offset load
    const int lo = dst_row0;               // 0..4
    const int hi = H_ - 1 - src_row0;      // 79..83

    // wait (acquire) for the bulk load
    asm volatile(
        "{\n\t"
        ".reg .pred P;\n\t"
        "WAIT_%=: \n\t"
        "mbarrier.try_wait.parity.acquire.cta.shared::cta.b64 P, [%0], 0, 0x989680;\n\t"
        "@P bra.uni DONE_%=;\n\t"
        "bra.uni WAIT_%=;\n\t"
        "DONE_%=: \n\t"
        "}"
        :: "r"(bar) : "memory");

    // ---- phase A: rows j0 + 3k, k = 0..13 (rows 0..41) ----
    {
        float v[14];
        #pragma unroll
        for (int k = 0; k < 14; k++) {
            const int j = j0 + 3 * k;
            const int r = min(max(j, lo), hi);     // vertical clamp on smem row
            v[k] = s[r * W_ + srcx];
        }
        __syncthreads();                           // all A-reads before A-writes
        #pragma unroll
        for (int k = 0; k < 14; k++) {
            const int j = j0 + 3 * k;
            s[j * W_ + i] = v[k];
        }
    }
    __syncthreads();                               // A committed, visible to tid 0

    // overlap: store first half while phase B computes
    if (tid == 0) {
        asm volatile("fence.proxy.async;" ::: "memory");
        asm volatile(
            "cp.async.bulk.global.shared::cta.bulk_group [%0], [%1], %2;"
            :: "l"(out + (long)nc * SLICE), "r"(smem_u32(s)),
               "r"((uint32_t)HALF_BYTES)
            : "memory");
        asm volatile("cp.async.bulk.commit_group;" ::: "memory");
    }

    // ---- phase B: rows j0 + 3k, k = 14..27 (rows 42..83) ----
    // B reads rows >= 42 (own rows and hi >= 79): untouched by phase A writes.
    {
        float v[14];
        #pragma unroll
        for (int k = 0; k < 14; k++) {
            const int j = j0 + 3 * (k + 14);
            const int r = min(max(j, lo), hi);
            v[k] = s[r * W_ + srcx];
        }
        __syncthreads();                           // all B-reads before B-writes
        #pragma unroll
        for (int k = 0; k < 14; k++) {
            const int j = j0 + 3 * (k + 14);
            s[j * W_ + i] = v[k];
        }
    }
    __syncthreads();                               // B committed, visible to tid 0

    if (tid == 0) {
        asm volatile("fence.proxy.async;" ::: "memory");
        asm volatile(
            "cp.async.bulk.global.shared::cta.bulk_group [%0], [%1], %2;"
            :: "l"(out + (long)nc * SLICE + HALF_ROWS * W_),
               "r"(smem_u32(s + HALF_ROWS * W_)),
               "r"((uint32_t)(SLICE_BYTES - HALF_BYTES))
            : "memory");
        asm volatile("cp.async.bulk.commit_group;" ::: "memory");
        asm volatile("cp.async.bulk.wait_group 0;" ::: "memory");
    }
}

extern "C" void kernel_launch(void* const* d_in, const int* in_sizes, int n_in,
                              void* d_out, int out_size)
{
    const float* x     = (const float*)d_in[0];
    const int*   shift = (const int*)  d_in[1];
    float* out = (float*)d_out;

    random_shift_r14_kernel<<<N_ * C_, THREADS>>>(x, shift, out);
}

// round 15
// speedup vs baseline: 1.0206x; 1.0206x over previous
#include <cuda_runtime.h>
#include <cstdint>

// RandomShiftsAug == integer shifted gather with edge clamp:
//   out[n,c,j,i] = x[n,c, clamp(j+sy-4,0,83), clamp(i+sx-4,0,83)]
//
// R15 = R13's global access pattern (FULL-slice, 128B-aligned cp.async.bulk in
// AND out -- the only configuration that raised the DRAM rate, 5.66 TB/s;
// R14 proved skewing the bulk base kills it) + double-buffered smem shuffle:
// read s_in, write s_out, so the in-place hazard disappears and all 8
// intermediate barriers collapse to one. 56KB/block -> 4 blocks/SM, same
// effective occupancy as R13 (51%) but half the serial depth per block.

#define N_   512
#define C_   9
#define H_   84
#define W_   84
#define PAD_ 4

#define SLICE       (H_ * W_)          // 7056 floats
#define SLICE_BYTES (SLICE * 4)        // 28224 B
#define THREADS     252                // 84 cols x 3 row phases
#define KITER       28                 // rows per thread

__device__ __forceinline__ uint32_t smem_u32(const void* p) {
    return (uint32_t)__cvta_generic_to_shared(p);
}

__global__ __launch_bounds__(THREADS) void random_shift_r15_kernel(
    const float* __restrict__ x,
    const int*   __restrict__ shift,
    float*       __restrict__ out)
{
    __shared__ alignas(128) float s_in[SLICE];
    __shared__ alignas(128) float s_out[SLICE];
    __shared__ alignas(8)  uint64_t mbar;

    const int nc  = blockIdx.x;            // (n*C + c)
    const int n   = nc / C_;
    const int tid = threadIdx.x;

    const uint32_t bar = smem_u32(&mbar);

    if (tid == 0) {
        asm volatile("mbarrier.init.shared.b64 [%0], 1;" :: "r"(bar));
    }
    __syncthreads();

    if (tid == 0) {
        asm volatile("mbarrier.arrive.expect_tx.shared.b64 _, [%0], %1;"
                     :: "r"(bar), "r"((uint32_t)SLICE_BYTES) : "memory");
        asm volatile(
            "cp.async.bulk.shared::cluster.global.mbarrier::complete_tx::bytes "
            "[%0], [%1], %2, [%3];"
            :: "r"(smem_u32(s_in)), "l"(x + (long)nc * SLICE),
               "r"((uint32_t)SLICE_BYTES), "r"(bar)
            : "memory");
    }

    const int sx = __ldg(&shift[2 * n + 0]) - PAD_;   // [-4,4], block-uniform
    const int sy = __ldg(&shift[2 * n + 1]) - PAD_;

    const int i  = tid % W_;               // column, 0..83
    const int j0 = tid / W_;               // row phase, 0..2
    const int srcx = min(max(i + sx, 0), W_ - 1);

    // wait (acquire) for the bulk load
    asm volatile(
        "{\n\t"
        ".reg .pred P;\n\t"
        "WAIT_%=: \n\t"
        "mbarrier.try_wait.parity.acquire.cta.shared::cta.b64 P, [%0], 0, 0x989680;\n\t"
        "@P bra.uni DONE_%=;\n\t"
        "bra.uni WAIT_%=;\n\t"
        "DONE_%=: \n\t"
        "}"
        :: "r"(bar) : "memory");

    // ---- shuffle s_in -> s_out: no hazards, no intermediate barriers ----
    #pragma unroll
    for (int k = 0; k < KITER; k++) {
        const int j    = j0 + 3 * k;                    // output row
        const int srcy = min(max(j + sy, 0), H_ - 1);
        s_out[j * W_ + i] = s_in[srcy * W_ + srcx];
    }
    __syncthreads();                                    // s_out complete

    // ---- full-slice aligned bulk store ----
    if (tid == 0) {
        asm volatile("fence.proxy.async;" ::: "memory");
        asm volatile(
            "cp.async.bulk.global.shared::cta.bulk_group [%0], [%1], %2;"
            :: "l"(out + (long)nc * SLICE), "r"(smem_u32(s_out)),
               "r"((uint32_t)SLICE_BYTES)
            : "memory");
        asm volatile("cp.async.bulk.commit_group;" ::: "memory");
        asm volatile("cp.async.bulk.wait_group 0;" ::: "memory");
    }
}

extern "C" void kernel_launch(void* const* d_in, const int* in_sizes, int n_in,
                              void* d_out, int out_size)
{
    const float* x     = (const float*)d_in[0];
    const int*   shift = (const int*)  d_in[1];
    float* out = (float*)d_out;

    random_shift_r15_kernel<<<N_ * C_, THREADS>>>(x, shift, out);
}